// round 1
// baseline (speedup 1.0000x reference)
#include <cuda_runtime.h>
#include <math.h>

#define NT   8192      // B*L tokens
#define DD   256       // D
#define FF   8         // F
#define DFE  64        // DF
#define DIN  320       // D + DF
#define DR   256
#define EE   8
#define DH   512

// ---------------- scratch (device globals; no allocation) ----------------
__device__ __align__(16) float g_x[NT * DIN];        // concat(hidden, feat_emb)
__device__ int                 g_cnt[EE];            // per-expert assignment count
__device__ int                 g_tok[EE * NT];       // token | (slot<<31)
__device__ float               g_w[EE * NT];         // gate weight for assignment
__device__ __align__(16) float g_part[2 * NT * DD];  // slot-0 / slot-1 partials

__device__ __forceinline__ float gelu_tanh(float v) {
    // jax.nn.gelu default (approximate=True): 0.5*x*(1+tanh(sqrt(2/pi)*(x+0.044715 x^3)))
    float u = 0.7978845608028654f * (v + 0.044715f * v * v * v);
    return 0.5f * v * (1.0f + tanhf(u));
}

// ---------------- K0: reset counters ----------------
__global__ void k_init() {
    if (threadIdx.x < EE) g_cnt[threadIdx.x] = 0;
}

// ---------------- K1: build x = concat(hidden, feat @ W_feat + b_feat) ----------------
__global__ void k_build_x(const float* __restrict__ hidden,
                          const float* __restrict__ feat,
                          const float* __restrict__ Wf,
                          const float* __restrict__ bf) {
    int tok = blockIdx.x;
    int t = threadIdx.x;
    if (t < DD) {
        g_x[tok * DIN + t] = hidden[tok * DD + t];
    } else {
        int j = t - DD;
        float acc = bf[j];
        float fv[FF];
#pragma unroll
        for (int k = 0; k < FF; k++) fv[k] = feat[tok * FF + k];
#pragma unroll
        for (int k = 0; k < FF; k++) acc += fv[k] * Wf[k * DFE + j];
        g_x[tok * DIN + DD + j] = acc;
    }
}

// ---------------- K2: router (hr = gelu(x@Wr1+br1); logits = hr@Wr2+br2; top-2 gating) ----
// CTA = 32 tokens, 256 threads. smem: xT[320][33] then reused as hrT[256][33];
// weight chunk buffer 32*256 floats, reused for Wr2 + logits staging.
#define R_SMEM_FLOATS (320 * 33 + 32 * 256)
__global__ __launch_bounds__(256, 2) void k_router(
    const float* __restrict__ Wr1, const float* __restrict__ br1,
    const float* __restrict__ Wr2, const float* __restrict__ br2,
    float* __restrict__ out) {
    extern __shared__ float sm[];
    float* xT  = sm;                // 320*33 = 10560 floats
    float* wch = sm + 320 * 33;     // 32*256 = 8192 floats
    float* hrT = sm;                // reuse xT region: 256*33 = 8448 <= 10560
    float* ws2 = wch;               // 256*8 = 2048
    float* lg  = wch + 2048;        // 32*8

    int tid  = threadIdx.x;
    int base = blockIdx.x * 32;

    // gather xT[k][r] (stride-33 row: conflict-free, rows token-minor)
    for (int idx = tid; idx < 32 * DIN; idx += 256) {
        int r = idx / DIN;
        int k = idx - r * DIN;
        xT[k * 33 + r] = g_x[(base + r) * DIN + k];
    }

    int tg = tid >> 5;   // token group: tokens 4tg..4tg+3
    int cg = tid & 31;   // column group: cols 4cg+128m

    float acc[2][4][4];
#pragma unroll
    for (int m = 0; m < 2; m++)
#pragma unroll
        for (int tt = 0; tt < 4; tt++)
#pragma unroll
            for (int j = 0; j < 4; j++) acc[m][tt][j] = 0.f;

    for (int kc = 0; kc < DIN; kc += 32) {
#pragma unroll
        for (int i = 0; i < 32; i++) {
            int idx = tid + i * 256;
            int kk = idx >> 8;
            int c  = idx & 255;
            wch[kk * 256 + c] = Wr1[(kc + kk) * DR + c];
        }
        __syncthreads();
#pragma unroll 2
        for (int k = 0; k < 32; k++) {
            float xv[4];
#pragma unroll
            for (int tt = 0; tt < 4; tt++) xv[tt] = xT[(kc + k) * 33 + 4 * tg + tt];
#pragma unroll
            for (int m = 0; m < 2; m++) {
                float4 wq = *(const float4*)&wch[k * 256 + 128 * m + 4 * cg];
#pragma unroll
                for (int tt = 0; tt < 4; tt++) {
                    acc[m][tt][0] += xv[tt] * wq.x;
                    acc[m][tt][1] += xv[tt] * wq.y;
                    acc[m][tt][2] += xv[tt] * wq.z;
                    acc[m][tt][3] += xv[tt] * wq.w;
                }
            }
        }
        __syncthreads();
    }

    // bias + gelu -> hrT[col][row] (overwrites xT region; all xT reads done)
#pragma unroll
    for (int m = 0; m < 2; m++)
#pragma unroll
        for (int j = 0; j < 4; j++) {
            int col = 4 * cg + 128 * m + j;
            float b = br1[col];
#pragma unroll
            for (int tt = 0; tt < 4; tt++)
                hrT[col * 33 + 4 * tg + tt] = gelu_tanh(acc[m][tt][j] + b);
        }
    // stage Wr2
    for (int idx = tid; idx < DR * EE; idx += 256) ws2[idx] = Wr2[idx];
    __syncthreads();

    // logits: warp e handles expert e, lane r handles token r
    {
        int e = tid >> 5;
        int r = tid & 31;
        float lacc = br2[e];
#pragma unroll 4
        for (int k = 0; k < DR; k++) lacc += hrT[k * 33 + r] * ws2[k * EE + e];
        lg[r * EE + e] = lacc;
        // TEMP == 1.0
        out[(size_t)NT * DD + (size_t)NT * EE + (size_t)(base + r) * EE + e] = lacc;
    }
    __syncthreads();

    // top-2 gating per token (thread r < 32)
    if (tid < 32) {
        int r = tid;
        int gtok = base + r;
        float v[EE];
#pragma unroll
        for (int e = 0; e < EE; e++) v[e] = lg[r * EE + e];
        int i0 = 0;
#pragma unroll
        for (int e = 1; e < EE; e++)
            if (v[e] > v[i0]) i0 = e;   // strict > : earliest index wins ties (matches lax.top_k)
        int i1 = (i0 == 0) ? 1 : 0;
#pragma unroll
        for (int e = 0; e < EE; e++) {
            if (e == i0) continue;
            if (v[e] > v[i1]) i1 = e;
        }
        float t  = expf(v[i1] - v[i0]);
        float s  = 1.0f + t;
        float w0 = 1.0f / s;
        float w1 = t / s;
        // gate_weights
        float* gw = out + (size_t)NT * DD + (size_t)gtok * EE;
#pragma unroll
        for (int e = 0; e < EE; e++)
            gw[e] = (e == i0) ? w0 : ((e == i1) ? w1 : 0.0f);
        // append to expert lists
        int p0 = atomicAdd(&g_cnt[i0], 1);
        g_tok[i0 * NT + p0] = gtok;                 // slot 0
        g_w[i0 * NT + p0]   = w0;
        int p1 = atomicAdd(&g_cnt[i1], 1);
        g_tok[i1 * NT + p1] = gtok | (1 << 31);     // slot 1
        g_w[i1 * NT + p1]   = w1;
    }
}

// ---------------- K3: expert MLP on gathered tokens (both layers fused per CTA) ------
// CTA = (expert e, 32 assigned tokens). Layer1: [32,320]@[320,512] -> gelu (heT in smem)
// Layer2: [32,512]@[512,256] -> scaled write into slot partial buffer.
#define E_SMEM_FLOATS (320 * 33 + 512 * 33)
__global__ __launch_bounds__(256, 2) void k_expert(
    const float* __restrict__ We1, const float* __restrict__ be1,
    const float* __restrict__ We2, const float* __restrict__ be2) {
    extern __shared__ float sm[];
    float* xT  = sm;             // 320*33 = 10560 floats; reused for We2 chunk (32*256)
    float* wch = sm + 320 * 33;  // 512*33 = 16896 floats: We1 chunk (32*512) then heT
    __shared__ int   s_tok[32];
    __shared__ int   s_slot[32];
    __shared__ float s_w[32];

    int e    = blockIdx.y;
    int cnt  = g_cnt[e];
    int base = blockIdx.x * 32;
    if (base >= cnt) return;
    int nrows = min(32, cnt - base);

    int tid = threadIdx.x;
    if (tid < 32) {
        int r = tid;
        if (r < nrows) {
            int ent  = g_tok[e * NT + base + r];
            s_tok[r]  = ent & 0x7FFFFFFF;
            s_slot[r] = (ent >> 31) & 1;
            s_w[r]    = g_w[e * NT + base + r];
        } else {
            s_tok[r] = 0; s_slot[r] = 0; s_w[r] = 0.f;
        }
    }
    __syncthreads();

    // gather xT
    for (int idx = tid; idx < 32 * DIN; idx += 256) {
        int r = idx / DIN;
        int k = idx - r * DIN;
        xT[k * 33 + r] = g_x[s_tok[r] * DIN + k];
    }

    int tg = tid >> 5;
    int cg = tid & 31;

    // ---- layer 1: acc[4 quads m][4 tok][4 col] over K=320 ----
    float acc[4][4][4];
#pragma unroll
    for (int m = 0; m < 4; m++)
#pragma unroll
        for (int tt = 0; tt < 4; tt++)
#pragma unroll
            for (int j = 0; j < 4; j++) acc[m][tt][j] = 0.f;

    const float* W1 = We1 + (size_t)e * DIN * DH;
    for (int kc = 0; kc < DIN; kc += 32) {
#pragma unroll
        for (int i = 0; i < 64; i++) {
            int idx = tid + i * 256;
            int kk = idx >> 9;
            int c  = idx & 511;
            wch[kk * 512 + c] = W1[(size_t)(kc + kk) * DH + c];
        }
        __syncthreads();
#pragma unroll 2
        for (int k = 0; k < 32; k++) {
            float xv[4];
#pragma unroll
            for (int tt = 0; tt < 4; tt++) xv[tt] = xT[(kc + k) * 33 + 4 * tg + tt];
#pragma unroll
            for (int m = 0; m < 4; m++) {
                float4 wq = *(const float4*)&wch[k * 512 + 128 * m + 4 * cg];
#pragma unroll
                for (int tt = 0; tt < 4; tt++) {
                    acc[m][tt][0] += xv[tt] * wq.x;
                    acc[m][tt][1] += xv[tt] * wq.y;
                    acc[m][tt][2] += xv[tt] * wq.z;
                    acc[m][tt][3] += xv[tt] * wq.w;
                }
            }
        }
        __syncthreads();
    }

    // bias + gelu -> heT[col][row] in wch (all wch/xT reads done at last sync)
#pragma unroll
    for (int m = 0; m < 4; m++)
#pragma unroll
        for (int j = 0; j < 4; j++) {
            int col = 4 * cg + 128 * m + j;
            float b = be1[e * DH + col];
#pragma unroll
            for (int tt = 0; tt < 4; tt++)
                wch[col * 33 + 4 * tg + tt] = gelu_tanh(acc[m][tt][j] + b);
        }
    __syncthreads();

    // ---- layer 2: acc2[2][4][4] over K=512, heT in wch, We2 chunk staged in xT ----
    float acc2[2][4][4];
#pragma unroll
    for (int m = 0; m < 2; m++)
#pragma unroll
        for (int tt = 0; tt < 4; tt++)
#pragma unroll
            for (int j = 0; j < 4; j++) acc2[m][tt][j] = 0.f;

    const float* W2 = We2 + (size_t)e * DH * DD;
    float* w2 = xT;
    for (int kc = 0; kc < DH; kc += 32) {
#pragma unroll
        for (int i = 0; i < 32; i++) {
            int idx = tid + i * 256;
            int kk = idx >> 8;
            int c  = idx & 255;
            w2[kk * 256 + c] = W2[(size_t)(kc + kk) * DD + c];
        }
        __syncthreads();
#pragma unroll 2
        for (int k = 0; k < 32; k++) {
            float hv[4];
#pragma unroll
            for (int tt = 0; tt < 4; tt++) hv[tt] = wch[(kc + k) * 33 + 4 * tg + tt];
#pragma unroll
            for (int m = 0; m < 2; m++) {
                float4 wq = *(const float4*)&w2[k * 256 + 128 * m + 4 * cg];
#pragma unroll
                for (int tt = 0; tt < 4; tt++) {
                    acc2[m][tt][0] += hv[tt] * wq.x;
                    acc2[m][tt][1] += hv[tt] * wq.y;
                    acc2[m][tt][2] += hv[tt] * wq.z;
                    acc2[m][tt][3] += hv[tt] * wq.w;
                }
            }
        }
        __syncthreads();
    }

    // epilogue: scaled write into slot partial buffer (float4, coalesced)
#pragma unroll
    for (int m = 0; m < 2; m++)
#pragma unroll
        for (int tt = 0; tt < 4; tt++) {
            int r = 4 * tg + tt;
            if (r < nrows) {
                int col0 = 4 * cg + 128 * m;
                float wgt = s_w[r];
                float4 o;
                o.x = wgt * (acc2[m][tt][0] + be2[e * DD + col0 + 0]);
                o.y = wgt * (acc2[m][tt][1] + be2[e * DD + col0 + 1]);
                o.z = wgt * (acc2[m][tt][2] + be2[e * DD + col0 + 2]);
                o.w = wgt * (acc2[m][tt][3] + be2[e * DD + col0 + 3]);
                *(float4*)&g_part[((size_t)s_slot[r] * NT + s_tok[r]) * DD + col0] = o;
            }
        }
}

// ---------------- K4: combine the two slot partials -> stage_delta ----------------
__global__ void k_combine(float* __restrict__ out) {
    int i = blockIdx.x * blockDim.x + threadIdx.x;
    const float4* p0 = (const float4*)g_part;
    const float4* p1 = (const float4*)(g_part + (size_t)NT * DD);
    float4 a = p0[i], b = p1[i];
    float4 r;
    r.x = a.x + b.x; r.y = a.y + b.y; r.z = a.z + b.z; r.w = a.w + b.w;
    ((float4*)out)[i] = r;
}

// ---------------- launch ----------------
extern "C" void kernel_launch(void* const* d_in, const int* in_sizes, int n_in,
                              void* d_out, int out_size) {
    const float* hidden = (const float*)d_in[0];
    const float* feat   = (const float*)d_in[1];
    const float* Wf     = (const float*)d_in[2];
    const float* bf     = (const float*)d_in[3];
    const float* Wr1    = (const float*)d_in[4];
    const float* br1    = (const float*)d_in[5];
    const float* Wr2    = (const float*)d_in[6];
    const float* br2    = (const float*)d_in[7];
    const float* We1    = (const float*)d_in[8];
    const float* be1    = (const float*)d_in[9];
    const float* We2    = (const float*)d_in[10];
    const float* be2    = (const float*)d_in[11];
    float* out = (float*)d_out;

    const int r_smem = R_SMEM_FLOATS * 4;   // 75008 B
    const int e_smem = E_SMEM_FLOATS * 4;   // 109824 B
    cudaFuncSetAttribute(k_router, cudaFuncAttributeMaxDynamicSharedMemorySize, r_smem);
    cudaFuncSetAttribute(k_expert, cudaFuncAttributeMaxDynamicSharedMemorySize, e_smem);

    k_init<<<1, 32>>>();
    k_build_x<<<NT, DIN>>>(hidden, feat, Wf, bf);
    k_router<<<NT / 32, 256, r_smem>>>(Wr1, br1, Wr2, br2, out);
    dim3 ge(NT / 32, EE);
    k_expert<<<ge, 256, e_smem>>>(We1, be1, We2, be2);
    k_combine<<<(NT * DD / 4) / 256, 256>>>(out);
}

// round 2
// speedup vs baseline: 1.0033x; 1.0033x over previous
#include <cuda_runtime.h>
#include <math.h>

#define NT   8192      // B*L tokens
#define DD   256       // D
#define FF   8         // F
#define DFE  64        // DF
#define DIN  320       // D + DF
#define DR   256
#define EE   8
#define DH   512

// ---------------- scratch (device globals; no allocation) ----------------
__device__ __align__(16) float g_x[NT * DIN];        // concat(hidden, feat_emb)
__device__ int                 g_cnt[EE];            // per-expert assignment count
__device__ int                 g_tok[EE * NT];       // token | (slot<<31)
__device__ float               g_w[EE * NT];         // gate weight for assignment
__device__ __align__(16) float g_part[2 * NT * DD];  // slot-0 / slot-1 partials

__device__ __forceinline__ float gelu_tanh(float v) {
    // jax.nn.gelu default (approximate=True): 0.5*x*(1+tanh(sqrt(2/pi)*(x+0.044715 x^3)))
    float u = 0.7978845608028654f * (v + 0.044715f * v * v * v);
    return 0.5f * v * (1.0f + tanhf(u));
}

// ---------------- K0: reset counters ----------------
__global__ void k_init() {
    if (threadIdx.x < EE) g_cnt[threadIdx.x] = 0;
}

// ---------------- K1: build x = concat(hidden, feat @ W_feat + b_feat) ----------------
__global__ void k_build_x(const float* __restrict__ hidden,
                          const float* __restrict__ feat,
                          const float* __restrict__ Wf,
                          const float* __restrict__ bf) {
    int tok = blockIdx.x;
    int t = threadIdx.x;
    if (t < DD) {
        g_x[tok * DIN + t] = hidden[tok * DD + t];
    } else {
        int j = t - DD;
        float acc = bf[j];
        float fv[FF];
#pragma unroll
        for (int k = 0; k < FF; k++) fv[k] = feat[tok * FF + k];
#pragma unroll
        for (int k = 0; k < FF; k++) acc += fv[k] * Wf[k * DFE + j];
        g_x[tok * DIN + DD + j] = acc;
    }
}

// ---------------- K2: router (hr = gelu(x@Wr1+br1); logits = hr@Wr2+br2; top-2 gating) ----
// CTA = 32 tokens, 256 threads. smem: xT[320][33] then reused as hrT[256][33];
// weight chunk buffer 32*256 floats, reused for Wr2 + logits staging.
#define R_SMEM_FLOATS (320 * 33 + 32 * 256)
__global__ __launch_bounds__(256, 2) void k_router(
    const float* __restrict__ Wr1, const float* __restrict__ br1,
    const float* __restrict__ Wr2, const float* __restrict__ br2,
    float* __restrict__ out) {
    extern __shared__ float sm[];
    float* xT  = sm;                // 320*33 = 10560 floats
    float* wch = sm + 320 * 33;     // 32*256 = 8192 floats
    float* hrT = sm;                // reuse xT region: 256*33 = 8448 <= 10560
    float* ws2 = wch;               // 256*8 = 2048
    float* lg  = wch + 2048;        // 32*8

    int tid  = threadIdx.x;
    int base = blockIdx.x * 32;

    // gather xT[k][r] (stride-33 row: conflict-free, rows token-minor)
    for (int idx = tid; idx < 32 * DIN; idx += 256) {
        int r = idx / DIN;
        int k = idx - r * DIN;
        xT[k * 33 + r] = g_x[(base + r) * DIN + k];
    }

    int tg = tid >> 5;   // token group: tokens 4tg..4tg+3
    int cg = tid & 31;   // column group: cols 4cg+128m

    float acc[2][4][4];
#pragma unroll
    for (int m = 0; m < 2; m++)
#pragma unroll
        for (int tt = 0; tt < 4; tt++)
#pragma unroll
            for (int j = 0; j < 4; j++) acc[m][tt][j] = 0.f;

    for (int kc = 0; kc < DIN; kc += 32) {
#pragma unroll
        for (int i = 0; i < 32; i++) {
            int idx = tid + i * 256;
            int kk = idx >> 8;
            int c  = idx & 255;
            wch[kk * 256 + c] = Wr1[(kc + kk) * DR + c];
        }
        __syncthreads();
#pragma unroll 2
        for (int k = 0; k < 32; k++) {
            float xv[4];
#pragma unroll
            for (int tt = 0; tt < 4; tt++) xv[tt] = xT[(kc + k) * 33 + 4 * tg + tt];
#pragma unroll
            for (int m = 0; m < 2; m++) {
                float4 wq = *(const float4*)&wch[k * 256 + 128 * m + 4 * cg];
#pragma unroll
                for (int tt = 0; tt < 4; tt++) {
                    acc[m][tt][0] += xv[tt] * wq.x;
                    acc[m][tt][1] += xv[tt] * wq.y;
                    acc[m][tt][2] += xv[tt] * wq.z;
                    acc[m][tt][3] += xv[tt] * wq.w;
                }
            }
        }
        __syncthreads();
    }

    // bias + gelu -> hrT[col][row] (overwrites xT region; all xT reads done)
#pragma unroll
    for (int m = 0; m < 2; m++)
#pragma unroll
        for (int j = 0; j < 4; j++) {
            int col = 4 * cg + 128 * m + j;
            float b = br1[col];
#pragma unroll
            for (int tt = 0; tt < 4; tt++)
                hrT[col * 33 + 4 * tg + tt] = gelu_tanh(acc[m][tt][j] + b);
        }
    // stage Wr2
    for (int idx = tid; idx < DR * EE; idx += 256) ws2[idx] = Wr2[idx];
    __syncthreads();

    // logits: warp e handles expert e, lane r handles token r
    {
        int e = tid >> 5;
        int r = tid & 31;
        float lacc = br2[e];
#pragma unroll 4
        for (int k = 0; k < DR; k++) lacc += hrT[k * 33 + r] * ws2[k * EE + e];
        lg[r * EE + e] = lacc;
        // TEMP == 1.0
        out[(size_t)NT * DD + (size_t)NT * EE + (size_t)(base + r) * EE + e] = lacc;
    }
    __syncthreads();

    // top-2 gating per token (thread r < 32)
    if (tid < 32) {
        int r = tid;
        int gtok = base + r;
        float v[EE];
#pragma unroll
        for (int e = 0; e < EE; e++) v[e] = lg[r * EE + e];
        int i0 = 0;
#pragma unroll
        for (int e = 1; e < EE; e++)
            if (v[e] > v[i0]) i0 = e;   // strict > : earliest index wins ties (matches lax.top_k)
        int i1 = (i0 == 0) ? 1 : 0;
#pragma unroll
        for (int e = 0; e < EE; e++) {
            if (e == i0) continue;
            if (v[e] > v[i1]) i1 = e;
        }
        float t  = expf(v[i1] - v[i0]);
        float s  = 1.0f + t;
        float w0 = 1.0f / s;
        float w1 = t / s;
        // gate_weights
        float* gw = out + (size_t)NT * DD + (size_t)gtok * EE;
#pragma unroll
        for (int e = 0; e < EE; e++)
            gw[e] = (e == i0) ? w0 : ((e == i1) ? w1 : 0.0f);
        // append to expert lists
        int p0 = atomicAdd(&g_cnt[i0], 1);
        g_tok[i0 * NT + p0] = gtok;                 // slot 0
        g_w[i0 * NT + p0]   = w0;
        int p1 = atomicAdd(&g_cnt[i1], 1);
        g_tok[i1 * NT + p1] = gtok | (1 << 31);     // slot 1
        g_w[i1 * NT + p1]   = w1;
    }
}

// ---------------- K3: expert MLP on gathered tokens (both layers fused per CTA) ------
// CTA = (expert e, 32 assigned tokens). Layer1: [32,320]@[320,512] -> gelu (heT in smem)
// Layer2: [32,512]@[512,256] -> scaled write into slot partial buffer.
#define E_SMEM_FLOATS (320 * 33 + 512 * 33)
__global__ __launch_bounds__(256, 2) void k_expert(
    const float* __restrict__ We1, const float* __restrict__ be1,
    const float* __restrict__ We2, const float* __restrict__ be2) {
    extern __shared__ float sm[];
    float* xT  = sm;             // 320*33 = 10560 floats; reused for We2 chunk (32*256)
    float* wch = sm + 320 * 33;  // 512*33 = 16896 floats: We1 chunk (32*512) then heT
    __shared__ int   s_tok[32];
    __shared__ int   s_slot[32];
    __shared__ float s_w[32];

    int e    = blockIdx.y;
    int cnt  = g_cnt[e];
    int base = blockIdx.x * 32;
    if (base >= cnt) return;
    int nrows = min(32, cnt - base);

    int tid = threadIdx.x;
    if (tid < 32) {
        int r = tid;
        if (r < nrows) {
            int ent  = g_tok[e * NT + base + r];
            s_tok[r]  = ent & 0x7FFFFFFF;
            s_slot[r] = (ent >> 31) & 1;
            s_w[r]    = g_w[e * NT + base + r];
        } else {
            s_tok[r] = 0; s_slot[r] = 0; s_w[r] = 0.f;
        }
    }
    __syncthreads();

    // gather xT
    for (int idx = tid; idx < 32 * DIN; idx += 256) {
        int r = idx / DIN;
        int k = idx - r * DIN;
        xT[k * 33 + r] = g_x[s_tok[r] * DIN + k];
    }

    int tg = tid >> 5;
    int cg = tid & 31;

    // ---- layer 1: acc[4 quads m][4 tok][4 col] over K=320 ----
    float acc[4][4][4];
#pragma unroll
    for (int m = 0; m < 4; m++)
#pragma unroll
        for (int tt = 0; tt < 4; tt++)
#pragma unroll
            for (int j = 0; j < 4; j++) acc[m][tt][j] = 0.f;

    const float* W1 = We1 + (size_t)e * DIN * DH;
    for (int kc = 0; kc < DIN; kc += 32) {
#pragma unroll
        for (int i = 0; i < 64; i++) {
            int idx = tid + i * 256;
            int kk = idx >> 9;
            int c  = idx & 511;
            wch[kk * 512 + c] = W1[(size_t)(kc + kk) * DH + c];
        }
        __syncthreads();
#pragma unroll 2
        for (int k = 0; k < 32; k++) {
            float xv[4];
#pragma unroll
            for (int tt = 0; tt < 4; tt++) xv[tt] = xT[(kc + k) * 33 + 4 * tg + tt];
#pragma unroll
            for (int m = 0; m < 4; m++) {
                float4 wq = *(const float4*)&wch[k * 512 + 128 * m + 4 * cg];
#pragma unroll
                for (int tt = 0; tt < 4; tt++) {
                    acc[m][tt][0] += xv[tt] * wq.x;
                    acc[m][tt][1] += xv[tt] * wq.y;
                    acc[m][tt][2] += xv[tt] * wq.z;
                    acc[m][tt][3] += xv[tt] * wq.w;
                }
            }
        }
        __syncthreads();
    }

    // bias + gelu -> heT[col][row] in wch (all wch/xT reads done at last sync)
#pragma unroll
    for (int m = 0; m < 4; m++)
#pragma unroll
        for (int j = 0; j < 4; j++) {
            int col = 4 * cg + 128 * m + j;
            float b = be1[e * DH + col];
#pragma unroll
            for (int tt = 0; tt < 4; tt++)
                wch[col * 33 + 4 * tg + tt] = gelu_tanh(acc[m][tt][j] + b);
        }
    __syncthreads();

    // ---- layer 2: acc2[2][4][4] over K=512, heT in wch, We2 chunk staged in xT ----
    float acc2[2][4][4];
#pragma unroll
    for (int m = 0; m < 2; m++)
#pragma unroll
        for (int tt = 0; tt < 4; tt++)
#pragma unroll
            for (int j = 0; j < 4; j++) acc2[m][tt][j] = 0.f;

    const float* W2 = We2 + (size_t)e * DH * DD;
    float* w2 = xT;
    for (int kc = 0; kc < DH; kc += 32) {
#pragma unroll
        for (int i = 0; i < 32; i++) {
            int idx = tid + i * 256;
            int kk = idx >> 8;
            int c  = idx & 255;
            w2[kk * 256 + c] = W2[(size_t)(kc + kk) * DD + c];
        }
        __syncthreads();
#pragma unroll 2
        for (int k = 0; k < 32; k++) {
            float hv[4];
#pragma unroll
            for (int tt = 0; tt < 4; tt++) hv[tt] = wch[(kc + k) * 33 + 4 * tg + tt];
#pragma unroll
            for (int m = 0; m < 2; m++) {
                float4 wq = *(const float4*)&w2[k * 256 + 128 * m + 4 * cg];
#pragma unroll
                for (int tt = 0; tt < 4; tt++) {
                    acc2[m][tt][0] += hv[tt] * wq.x;
                    acc2[m][tt][1] += hv[tt] * wq.y;
                    acc2[m][tt][2] += hv[tt] * wq.z;
                    acc2[m][tt][3] += hv[tt] * wq.w;
                }
            }
        }
        __syncthreads();
    }

    // epilogue: scaled write into slot partial buffer (float4, coalesced)
#pragma unroll
    for (int m = 0; m < 2; m++)
#pragma unroll
        for (int tt = 0; tt < 4; tt++) {
            int r = 4 * tg + tt;
            if (r < nrows) {
                int col0 = 4 * cg + 128 * m;
                float wgt = s_w[r];
                float4 o;
                o.x = wgt * (acc2[m][tt][0] + be2[e * DD + col0 + 0]);
                o.y = wgt * (acc2[m][tt][1] + be2[e * DD + col0 + 1]);
                o.z = wgt * (acc2[m][tt][2] + be2[e * DD + col0 + 2]);
                o.w = wgt * (acc2[m][tt][3] + be2[e * DD + col0 + 3]);
                *(float4*)&g_part[((size_t)s_slot[r] * NT + s_tok[r]) * DD + col0] = o;
            }
        }
}

// ---------------- K4: combine the two slot partials -> stage_delta ----------------
__global__ void k_combine(float* __restrict__ out) {
    int i = blockIdx.x * blockDim.x + threadIdx.x;
    const float4* p0 = (const float4*)g_part;
    const float4* p1 = (const float4*)(g_part + (size_t)NT * DD);
    float4 a = p0[i], b = p1[i];
    float4 r;
    r.x = a.x + b.x; r.y = a.y + b.y; r.z = a.z + b.z; r.w = a.w + b.w;
    ((float4*)out)[i] = r;
}

// ---------------- launch ----------------
extern "C" void kernel_launch(void* const* d_in, const int* in_sizes, int n_in,
                              void* d_out, int out_size) {
    const float* hidden = (const float*)d_in[0];
    const float* feat   = (const float*)d_in[1];
    const float* Wf     = (const float*)d_in[2];
    const float* bf     = (const float*)d_in[3];
    const float* Wr1    = (const float*)d_in[4];
    const float* br1    = (const float*)d_in[5];
    const float* Wr2    = (const float*)d_in[6];
    const float* br2    = (const float*)d_in[7];
    const float* We1    = (const float*)d_in[8];
    const float* be1    = (const float*)d_in[9];
    const float* We2    = (const float*)d_in[10];
    const float* be2    = (const float*)d_in[11];
    float* out = (float*)d_out;

    const int r_smem = R_SMEM_FLOATS * 4;   // 75008 B
    const int e_smem = E_SMEM_FLOATS * 4;   // 109824 B
    cudaFuncSetAttribute(k_router, cudaFuncAttributeMaxDynamicSharedMemorySize, r_smem);
    cudaFuncSetAttribute(k_expert, cudaFuncAttributeMaxDynamicSharedMemorySize, e_smem);

    k_init<<<1, 32>>>();
    k_build_x<<<NT, DIN>>>(hidden, feat, Wf, bf);
    k_router<<<NT / 32, 256, r_smem>>>(Wr1, br1, Wr2, br2, out);
    dim3 ge(NT / 32, EE);
    k_expert<<<ge, 256, e_smem>>>(We1, be1, We2, be2);
    k_combine<<<(NT * DD / 4) / 256, 256>>>(out);
}

// round 4
// speedup vs baseline: 1.2622x; 1.2580x over previous
#include <cuda_runtime.h>
#include <cuda_bf16.h>
#include <math.h>
#include <stdint.h>

#define NT   8192
#define DD   256
#define FF   8
#define DFE  64
#define DIN  320
#define DR   256
#define EE   8
#define DH   512

// ---------------- device-global scratch ----------------
__device__ __align__(16) float g_x[NT * DIN];
__device__ int                 g_cnt[EE];
__device__ int                 g_tok[EE * NT];
__device__ float               g_w[EE * NT];
__device__ __align__(16) float g_part[2 * NT * DD];
__device__ __align__(16) __nv_bfloat16 g_xh[NT * DIN];
__device__ __align__(16) __nv_bfloat16 g_xl[NT * DIN];
// he splits, keyed by (slot*NT + token)
__device__ __align__(16) __nv_bfloat16 g_heh[2 * NT * DH];
__device__ __align__(16) __nv_bfloat16 g_hel[2 * NT * DH];
// pre-transposed n-major weights: B1 [e][kc=5][n=512][k=64], B2 [e][kc=8][n=256][k=64]
__device__ __align__(16) __nv_bfloat16 g_B1h[EE * 5 * 512 * 64];
__device__ __align__(16) __nv_bfloat16 g_B1l[EE * 5 * 512 * 64];
__device__ __align__(16) __nv_bfloat16 g_B2h[EE * 8 * 256 * 64];
__device__ __align__(16) __nv_bfloat16 g_B2l[EE * 8 * 256 * 64];

// ---------------- helpers ----------------
__device__ __forceinline__ float gelu_tanh(float v) {
    float u = 0.7978845608028654f * (v + 0.044715f * v * v * v);
    return 0.5f * v * (1.0f + tanhf(u));
}
__device__ __forceinline__ float gelu_fast(float v) {
    // 0.5 v (1+tanh(u)) == v * sigmoid(2u); __expf rel err ~1e-6
    float u = 0.7978845608028654f * (v + 0.044715f * v * v * v);
    return v / (1.0f + __expf(-2.0f * u));
}
__device__ __forceinline__ void mma_bf16(float* d, const uint32_t* a, const uint32_t* b) {
    asm volatile(
        "mma.sync.aligned.m16n8k16.row.col.f32.bf16.bf16.f32 "
        "{%0,%1,%2,%3}, {%4,%5,%6,%7}, {%8,%9}, {%0,%1,%2,%3};"
        : "+f"(d[0]), "+f"(d[1]), "+f"(d[2]), "+f"(d[3])
        : "r"(a[0]), "r"(a[1]), "r"(a[2]), "r"(a[3]), "r"(b[0]), "r"(b[1]));
}

// ---------------- K0: reset counters ----------------
__global__ void k_init() {
    if (threadIdx.x < EE) g_cnt[threadIdx.x] = 0;
}

// ---------------- K1: x = concat(hidden, feat @ W_feat + b_feat) + bf16 splits ------
__global__ void k_build_x(const float* __restrict__ hidden,
                          const float* __restrict__ feat,
                          const float* __restrict__ Wf,
                          const float* __restrict__ bf) {
    int tok = blockIdx.x;
    int t = threadIdx.x;
    float v;
    if (t < DD) {
        v = hidden[tok * DD + t];
    } else {
        int j = t - DD;
        float acc = bf[j];
#pragma unroll
        for (int k = 0; k < FF; k++) acc += feat[tok * FF + k] * Wf[k * DFE + j];
        v = acc;
    }
    g_x[tok * DIN + t] = v;
    __nv_bfloat16 h = __float2bfloat16(v);
    g_xh[tok * DIN + t] = h;
    g_xl[tok * DIN + t] = __float2bfloat16(v - __bfloat162float(h));
}

// ---------------- prep: transpose + split expert weights to n-major ----------------
__global__ void k_prep_w1(const float* __restrict__ We1) {
    __shared__ float tile[64][65];
    int e = blockIdx.z, kc = blockIdx.y, hb = blockIdx.x;
    int tid = threadIdx.x;
#pragma unroll
    for (int i = 0; i < 16; i++) {
        int li = i * 256 + tid;
        int ki = li >> 6, hi = li & 63;
        tile[ki][hi] = We1[((size_t)e * DIN + kc * 64 + ki) * DH + hb * 64 + hi];
    }
    __syncthreads();
#pragma unroll
    for (int i = 0; i < 16; i++) {
        int li = i * 256 + tid;
        int kk = li & 63, hr = li >> 6;
        float v = tile[kk][hr];
        __nv_bfloat16 h = __float2bfloat16(v);
        __nv_bfloat16 l = __float2bfloat16(v - __bfloat162float(h));
        size_t dst = (((size_t)(e * 5 + kc) * 512) + hb * 64 + hr) * 64 + kk;
        g_B1h[dst] = h;
        g_B1l[dst] = l;
    }
}

__global__ void k_prep_w2(const float* __restrict__ We2) {
    __shared__ float tile[64][65];
    int e = blockIdx.z, kc = blockIdx.y, ob = blockIdx.x;
    int tid = threadIdx.x;
#pragma unroll
    for (int i = 0; i < 16; i++) {
        int li = i * 256 + tid;
        int ki = li >> 6, oi = li & 63;
        tile[ki][oi] = We2[((size_t)e * DH + kc * 64 + ki) * DD + ob * 64 + oi];
    }
    __syncthreads();
#pragma unroll
    for (int i = 0; i < 16; i++) {
        int li = i * 256 + tid;
        int kk = li & 63, orr = li >> 6;
        float v = tile[kk][orr];
        __nv_bfloat16 h = __float2bfloat16(v);
        __nv_bfloat16 l = __float2bfloat16(v - __bfloat162float(h));
        size_t dst = (((size_t)(e * 8 + kc) * 256) + ob * 64 + orr) * 64 + kk;
        g_B2h[dst] = h;
        g_B2l[dst] = l;
    }
}

// ---------------- K2: router (logit-exact fp32 SIMT) ----------------
#define R_SMEM_FLOATS (320 * 33 + 32 * 256)
__global__ __launch_bounds__(256, 2) void k_router(
    const float* __restrict__ Wr1, const float* __restrict__ br1,
    const float* __restrict__ Wr2, const float* __restrict__ br2,
    float* __restrict__ out) {
    extern __shared__ float sm[];
    float* xT  = sm;
    float* wch = sm + 320 * 33;
    float* hrT = sm;
    float* ws2 = wch;
    float* lg  = wch + 2048;

    int tid  = threadIdx.x;
    int base = blockIdx.x * 32;

    for (int idx = tid; idx < 32 * DIN; idx += 256) {
        int r = idx / DIN;
        int k = idx - r * DIN;
        xT[k * 33 + r] = g_x[(base + r) * DIN + k];
    }

    int tg = tid >> 5;
    int cg = tid & 31;

    float acc[2][4][4];
#pragma unroll
    for (int m = 0; m < 2; m++)
#pragma unroll
        for (int tt = 0; tt < 4; tt++)
#pragma unroll
            for (int j = 0; j < 4; j++) acc[m][tt][j] = 0.f;

    for (int kc = 0; kc < DIN; kc += 32) {
#pragma unroll
        for (int i = 0; i < 32; i++) {
            int idx = tid + i * 256;
            int kk = idx >> 8;
            int c  = idx & 255;
            wch[kk * 256 + c] = Wr1[(kc + kk) * DR + c];
        }
        __syncthreads();
#pragma unroll 2
        for (int k = 0; k < 32; k++) {
            float xv[4];
#pragma unroll
            for (int tt = 0; tt < 4; tt++) xv[tt] = xT[(kc + k) * 33 + 4 * tg + tt];
#pragma unroll
            for (int m = 0; m < 2; m++) {
                float4 wq = *(const float4*)&wch[k * 256 + 128 * m + 4 * cg];
#pragma unroll
                for (int tt = 0; tt < 4; tt++) {
                    acc[m][tt][0] += xv[tt] * wq.x;
                    acc[m][tt][1] += xv[tt] * wq.y;
                    acc[m][tt][2] += xv[tt] * wq.z;
                    acc[m][tt][3] += xv[tt] * wq.w;
                }
            }
        }
        __syncthreads();
    }

#pragma unroll
    for (int m = 0; m < 2; m++)
#pragma unroll
        for (int j = 0; j < 4; j++) {
            int col = 4 * cg + 128 * m + j;
            float b = br1[col];
#pragma unroll
            for (int tt = 0; tt < 4; tt++)
                hrT[col * 33 + 4 * tg + tt] = gelu_tanh(acc[m][tt][j] + b);
        }
    for (int idx = tid; idx < DR * EE; idx += 256) ws2[idx] = Wr2[idx];
    __syncthreads();

    {
        int e = tid >> 5;
        int r = tid & 31;
        float lacc = br2[e];
#pragma unroll 4
        for (int k = 0; k < DR; k++) lacc += hrT[k * 33 + r] * ws2[k * EE + e];
        lg[r * EE + e] = lacc;
        out[(size_t)NT * DD + (size_t)NT * EE + (size_t)(base + r) * EE + e] = lacc;
    }
    __syncthreads();

    if (tid < 32) {
        int r = tid;
        int gtok = base + r;
        float v[EE];
#pragma unroll
        for (int e = 0; e < EE; e++) v[e] = lg[r * EE + e];
        int i0 = 0;
#pragma unroll
        for (int e = 1; e < EE; e++)
            if (v[e] > v[i0]) i0 = e;
        int i1 = (i0 == 0) ? 1 : 0;
#pragma unroll
        for (int e = 0; e < EE; e++) {
            if (e == i0) continue;
            if (v[e] > v[i1]) i1 = e;
        }
        float t  = expf(v[i1] - v[i0]);
        float s  = 1.0f + t;
        float w0 = 1.0f / s;
        float w1 = t / s;
        float* gw = out + (size_t)NT * DD + (size_t)gtok * EE;
#pragma unroll
        for (int e = 0; e < EE; e++)
            gw[e] = (e == i0) ? w0 : ((e == i1) ? w1 : 0.0f);
        int p0 = atomicAdd(&g_cnt[i0], 1);
        g_tok[i0 * NT + p0] = gtok;
        g_w[i0 * NT + p0]   = w0;
        int p1 = atomicAdd(&g_cnt[i1], 1);
        g_tok[i1 * NT + p1] = gtok | (1 << 31);
        g_w[i1 * NT + p1]   = w1;
    }
}

// ---------------- HMMA expert layer 1: he = gelu(x@We1 + b1) ----------------
// CTA = (expert, 128 tokens). Warp grid 4(m)x2(n), warp tile 32x64, K-chunks of 64.
// smem: Ah/Al/Bh/Bl each [128][72] bf16 (stride 72 => conflict-free frag loads).
#define EXP_SMEM (4 * 128 * 72 * 2)
__global__ __launch_bounds__(256, 2) void k_expert1(const float* __restrict__ be1) {
    int e = blockIdx.y;
    int cnt = g_cnt[e];
    int base = blockIdx.x * 128;
    if (base >= cnt) return;
    int nrows = min(128, cnt - base);

    extern __shared__ char smraw[];
    char* Ah = smraw;
    char* Al = smraw + 18432;
    char* Bh = smraw + 36864;
    char* Bl = smraw + 55296;
    uint32_t* smw = (uint32_t*)smraw;
    const int OAL = 4608, OBH = 9216;

    __shared__ int s_tok[128];
    __shared__ int s_dst[128];

    int tid = threadIdx.x, wid = tid >> 5, lane = tid & 31;
    for (int r = tid; r < 128; r += 256) {
        int rr = (r < nrows) ? r : 0;
        int ent = g_tok[e * NT + base + rr];
        int tok = ent & 0x7FFFFFFF;
        s_tok[r] = tok;
        s_dst[r] = (r < nrows) ? (int)((((unsigned)ent) >> 31) * NT + tok) : -1;
    }
    __syncthreads();

    int wm = wid & 3, wn = wid >> 2, lq = lane >> 2, lr = lane & 3;

    for (int nc = 0; nc < 4; nc++) {
        float acc[2][8][4];
#pragma unroll
        for (int mt = 0; mt < 2; mt++)
#pragma unroll
            for (int nt = 0; nt < 8; nt++)
#pragma unroll
                for (int j = 0; j < 4; j++) acc[mt][nt][j] = 0.f;

        for (int kc = 0; kc < 5; kc++) {
            const char* B1h = (const char*)(g_B1h + (((size_t)(e * 5 + kc) * 512) + nc * 128) * 64);
            const char* B1l = (const char*)(g_B1l + (((size_t)(e * 5 + kc) * 512) + nc * 128) * 64);
#pragma unroll
            for (int i4 = 0; i4 < 4; i4++) {
                int i = tid + i4 * 256;
                int r = i >> 3, u = i & 7;
                const char* sx = (const char*)(g_xh + (size_t)s_tok[r] * DIN + kc * 64);
                const char* sl = (const char*)(g_xl + (size_t)s_tok[r] * DIN + kc * 64);
                *(uint4*)(Ah + r * 144 + u * 16) = *(const uint4*)(sx + u * 16);
                *(uint4*)(Al + r * 144 + u * 16) = *(const uint4*)(sl + u * 16);
                *(uint4*)(Bh + r * 144 + u * 16) = *(const uint4*)(B1h + r * 128 + u * 16);
                *(uint4*)(Bl + r * 144 + u * 16) = *(const uint4*)(B1l + r * 128 + u * 16);
            }
            __syncthreads();
#pragma unroll
            for (int s = 0; s < 4; s++) {
                uint32_t ah[2][4], al[2][4];
#pragma unroll
                for (int mt = 0; mt < 2; mt++) {
                    const uint32_t* p = smw + (wm * 32 + mt * 16 + lq) * 36 + s * 8 + lr;
                    ah[mt][0] = p[0]; ah[mt][1] = p[288]; ah[mt][2] = p[4]; ah[mt][3] = p[292];
                    const uint32_t* q = p + OAL;
                    al[mt][0] = q[0]; al[mt][1] = q[288]; al[mt][2] = q[4]; al[mt][3] = q[292];
                }
#pragma unroll
                for (int nt = 0; nt < 8; nt++) {
                    const uint32_t* p = smw + OBH + (wn * 64 + nt * 8 + lq) * 36 + s * 8 + lr;
                    uint32_t bh[2] = {p[0], p[4]};
                    uint32_t bl[2] = {p[4608], p[4612]};
#pragma unroll
                    for (int mt = 0; mt < 2; mt++) {
                        mma_bf16(acc[mt][nt], ah[mt], bh);
                        mma_bf16(acc[mt][nt], ah[mt], bl);
                        mma_bf16(acc[mt][nt], al[mt], bh);
                    }
                }
            }
            __syncthreads();
        }

        // epilogue: bias + gelu -> split -> g_heh/g_hel
        const float* b1 = be1 + e * DH + nc * 128;
#pragma unroll
        for (int mt = 0; mt < 2; mt++)
#pragma unroll
            for (int nt = 0; nt < 8; nt++) {
                int col = wn * 64 + nt * 8 + lr * 2;
                float bb0 = b1[col], bb1 = b1[col + 1];
#pragma unroll
                for (int h = 0; h < 2; h++) {
                    int row = wm * 32 + mt * 16 + lq + h * 8;
                    int dst = s_dst[row];
                    if (dst >= 0) {
                        float v0 = gelu_fast(acc[mt][nt][2 * h]     + bb0);
                        float v1 = gelu_fast(acc[mt][nt][2 * h + 1] + bb1);
                        __nv_bfloat16 h0 = __float2bfloat16(v0), h1 = __float2bfloat16(v1);
                        __nv_bfloat16 l0 = __float2bfloat16(v0 - __bfloat162float(h0));
                        __nv_bfloat16 l1 = __float2bfloat16(v1 - __bfloat162float(h1));
                        uint32_t ph = (uint32_t)__bfloat16_as_ushort(h0) | ((uint32_t)__bfloat16_as_ushort(h1) << 16);
                        uint32_t pl = (uint32_t)__bfloat16_as_ushort(l0) | ((uint32_t)__bfloat16_as_ushort(l1) << 16);
                        size_t widx = ((size_t)dst * DH + nc * 128 + col) >> 1;
                        ((uint32_t*)g_heh)[widx] = ph;
                        ((uint32_t*)g_hel)[widx] = pl;
                    }
                }
            }
    }
}

// ---------------- HMMA expert layer 2: eo = he@We2 + b2, gate-scaled ----------------
__global__ __launch_bounds__(256, 2) void k_expert2(const float* __restrict__ be2) {
    int e = blockIdx.y;
    int cnt = g_cnt[e];
    int base = blockIdx.x * 128;
    if (base >= cnt) return;
    int nrows = min(128, cnt - base);

    extern __shared__ char smraw[];
    char* Ah = smraw;
    char* Al = smraw + 18432;
    char* Bh = smraw + 36864;
    char* Bl = smraw + 55296;
    uint32_t* smw = (uint32_t*)smraw;
    const int OAL = 4608, OBH = 9216;

    __shared__ int   s_row[128];
    __shared__ int   s_dst[128];
    __shared__ float s_w[128];

    int tid = threadIdx.x, wid = tid >> 5, lane = tid & 31;
    for (int r = tid; r < 128; r += 256) {
        int rr = (r < nrows) ? r : 0;
        int ent = g_tok[e * NT + base + rr];
        int tok = ent & 0x7FFFFFFF;
        int herow = (int)((((unsigned)ent) >> 31) * NT + tok);
        s_row[r] = herow;
        s_dst[r] = (r < nrows) ? herow : -1;
        s_w[r]   = g_w[e * NT + base + rr];
    }
    __syncthreads();

    int wm = wid & 3, wn = wid >> 2, lq = lane >> 2, lr = lane & 3;

    for (int nc = 0; nc < 2; nc++) {
        float acc[2][8][4];
#pragma unroll
        for (int mt = 0; mt < 2; mt++)
#pragma unroll
            for (int nt = 0; nt < 8; nt++)
#pragma unroll
                for (int j = 0; j < 4; j++) acc[mt][nt][j] = 0.f;

        for (int kc = 0; kc < 8; kc++) {
            const char* B2h = (const char*)(g_B2h + (((size_t)(e * 8 + kc) * 256) + nc * 128) * 64);
            const char* B2l = (const char*)(g_B2l + (((size_t)(e * 8 + kc) * 256) + nc * 128) * 64);
#pragma unroll
            for (int i4 = 0; i4 < 4; i4++) {
                int i = tid + i4 * 256;
                int r = i >> 3, u = i & 7;
                const char* sx = (const char*)(g_heh + (size_t)s_row[r] * DH + kc * 64);
                const char* sl = (const char*)(g_hel + (size_t)s_row[r] * DH + kc * 64);
                *(uint4*)(Ah + r * 144 + u * 16) = *(const uint4*)(sx + u * 16);
                *(uint4*)(Al + r * 144 + u * 16) = *(const uint4*)(sl + u * 16);
                *(uint4*)(Bh + r * 144 + u * 16) = *(const uint4*)(B2h + r * 128 + u * 16);
                *(uint4*)(Bl + r * 144 + u * 16) = *(const uint4*)(B2l + r * 128 + u * 16);
            }
            __syncthreads();
#pragma unroll
            for (int s = 0; s < 4; s++) {
                uint32_t ah[2][4], al[2][4];
#pragma unroll
                for (int mt = 0; mt < 2; mt++) {
                    const uint32_t* p = smw + (wm * 32 + mt * 16 + lq) * 36 + s * 8 + lr;
                    ah[mt][0] = p[0]; ah[mt][1] = p[288]; ah[mt][2] = p[4]; ah[mt][3] = p[292];
                    const uint32_t* q = p + OAL;
                    al[mt][0] = q[0]; al[mt][1] = q[288]; al[mt][2] = q[4]; al[mt][3] = q[292];
                }
#pragma unroll
                for (int nt = 0; nt < 8; nt++) {
                    const uint32_t* p = smw + OBH + (wn * 64 + nt * 8 + lq) * 36 + s * 8 + lr;
                    uint32_t bh[2] = {p[0], p[4]};
                    uint32_t bl[2] = {p[4608], p[4612]};
#pragma unroll
                    for (int mt = 0; mt < 2; mt++) {
                        mma_bf16(acc[mt][nt], ah[mt], bh);
                        mma_bf16(acc[mt][nt], ah[mt], bl);
                        mma_bf16(acc[mt][nt], al[mt], bh);
                    }
                }
            }
            __syncthreads();
        }

        // epilogue: gate-scaled bias add -> g_part
        const float* b2 = be2 + e * DD + nc * 128;
#pragma unroll
        for (int mt = 0; mt < 2; mt++)
#pragma unroll
            for (int nt = 0; nt < 8; nt++) {
                int col = wn * 64 + nt * 8 + lr * 2;
                float bb0 = b2[col], bb1 = b2[col + 1];
#pragma unroll
                for (int h = 0; h < 2; h++) {
                    int row = wm * 32 + mt * 16 + lq + h * 8;
                    int dst = s_dst[row];
                    if (dst >= 0) {
                        float wgt = s_w[row];
                        float2 o;
                        o.x = wgt * (acc[mt][nt][2 * h]     + bb0);
                        o.y = wgt * (acc[mt][nt][2 * h + 1] + bb1);
                        *(float2*)&g_part[(size_t)dst * DD + nc * 128 + col] = o;
                    }
                }
            }
    }
}

// ---------------- K4: combine slot partials ----------------
__global__ void k_combine(float* __restrict__ out) {
    int i = blockIdx.x * blockDim.x + threadIdx.x;
    const float4* p0 = (const float4*)g_part;
    const float4* p1 = (const float4*)(g_part + (size_t)NT * DD);
    float4 a = p0[i], b = p1[i];
    float4 r;
    r.x = a.x + b.x; r.y = a.y + b.y; r.z = a.z + b.z; r.w = a.w + b.w;
    ((float4*)out)[i] = r;
}

// ---------------- launch ----------------
extern "C" void kernel_launch(void* const* d_in, const int* in_sizes, int n_in,
                              void* d_out, int out_size) {
    const float* hidden = (const float*)d_in[0];
    const float* feat   = (const float*)d_in[1];
    const float* Wf     = (const float*)d_in[2];
    const float* bf     = (const float*)d_in[3];
    const float* Wr1    = (const float*)d_in[4];
    const float* br1    = (const float*)d_in[5];
    const float* Wr2    = (const float*)d_in[6];
    const float* br2    = (const float*)d_in[7];
    const float* We1    = (const float*)d_in[8];
    const float* be1    = (const float*)d_in[9];
    const float* We2    = (const float*)d_in[10];
    const float* be2    = (const float*)d_in[11];
    float* out = (float*)d_out;

    const int r_smem = R_SMEM_FLOATS * 4;
    cudaFuncSetAttribute(k_router,  cudaFuncAttributeMaxDynamicSharedMemorySize, r_smem);
    cudaFuncSetAttribute(k_expert1, cudaFuncAttributeMaxDynamicSharedMemorySize, EXP_SMEM);
    cudaFuncSetAttribute(k_expert2, cudaFuncAttributeMaxDynamicSharedMemorySize, EXP_SMEM);

    k_init<<<1, 32>>>();
    k_build_x<<<NT, DIN>>>(hidden, feat, Wf, bf);
    k_prep_w1<<<dim3(8, 5, EE), 256>>>(We1);
    k_prep_w2<<<dim3(4, 8, EE), 256>>>(We2);
    k_router<<<NT / 32, 256, r_smem>>>(Wr1, br1, Wr2, br2, out);
    k_expert1<<<dim3(64, EE), 256, EXP_SMEM>>>(be1);
    k_expert2<<<dim3(64, EE), 256, EXP_SMEM>>>(be2);
    k_combine<<<(NT * DD / 4) / 256, 256>>>(out);
}

// round 5
// speedup vs baseline: 1.6430x; 1.3017x over previous
#include <cuda_runtime.h>
#include <cuda_bf16.h>
#include <math.h>
#include <stdint.h>

#define NT   8192
#define DD   256
#define FF   8
#define DFE  64
#define DIN  320
#define DR   256
#define EE   8
#define DH   512

// ---------------- device-global scratch ----------------
__device__ __align__(16) float g_x[NT * DIN];
__device__ int                 g_cnt[EE];
__device__ int                 g_tok[EE * NT];
__device__ float               g_w[EE * NT];
__device__ __align__(16) float g_part[2 * NT * DD];
__device__ __align__(16) __nv_bfloat16 g_xh[NT * DIN];
__device__ __align__(16) __nv_bfloat16 g_xl[NT * DIN];
__device__ __align__(16) __nv_bfloat16 g_heh[2 * NT * DH];
__device__ __align__(16) __nv_bfloat16 g_hel[2 * NT * DH];
// pre-transposed n-major weights: B1 [e][kc=5][n=512][k=64], B2 [e][kc=8][n=256][k=64]
__device__ __align__(16) __nv_bfloat16 g_B1h[EE * 5 * 512 * 64];
__device__ __align__(16) __nv_bfloat16 g_B1l[EE * 5 * 512 * 64];
__device__ __align__(16) __nv_bfloat16 g_B2h[EE * 8 * 256 * 64];
__device__ __align__(16) __nv_bfloat16 g_B2l[EE * 8 * 256 * 64];

// ---------------- helpers ----------------
__device__ __forceinline__ float gelu_tanh(float v) {
    float u = 0.7978845608028654f * (v + 0.044715f * v * v * v);
    return 0.5f * v * (1.0f + tanhf(u));
}
__device__ __forceinline__ float gelu_fast(float v) {
    float u = 0.7978845608028654f * (v + 0.044715f * v * v * v);
    return v / (1.0f + __expf(-2.0f * u));
}
__device__ __forceinline__ uint32_t smem_u32(const void* p) {
    uint32_t a;
    asm("{ .reg .u64 t; cvta.to.shared.u64 t, %1; cvt.u32.u64 %0, t; }" : "=r"(a) : "l"(p));
    return a;
}
__device__ __forceinline__ void mma_bf16(float* d, const uint32_t* a, const uint32_t* b) {
    asm volatile(
        "mma.sync.aligned.m16n8k16.row.col.f32.bf16.bf16.f32 "
        "{%0,%1,%2,%3}, {%4,%5,%6,%7}, {%8,%9}, {%0,%1,%2,%3};"
        : "+f"(d[0]), "+f"(d[1]), "+f"(d[2]), "+f"(d[3])
        : "r"(a[0]), "r"(a[1]), "r"(a[2]), "r"(a[3]), "r"(b[0]), "r"(b[1]));
}
__device__ __forceinline__ void ldsm_x4(uint32_t* r, uint32_t a) {
    asm volatile("ldmatrix.sync.aligned.m8n8.x4.shared.b16 {%0,%1,%2,%3}, [%4];"
        : "=r"(r[0]), "=r"(r[1]), "=r"(r[2]), "=r"(r[3]) : "r"(a));
}
__device__ __forceinline__ void cp16(uint32_t dst, const void* src) {
    asm volatile("cp.async.cg.shared.global [%0], [%1], 16;" :: "r"(dst), "l"(src));
}
__device__ __forceinline__ void cp_commit() {
    asm volatile("cp.async.commit_group;" ::: "memory");
}
__device__ __forceinline__ void cp_wait1() {
    asm volatile("cp.async.wait_group 1;" ::: "memory");
}
__device__ __forceinline__ void cp_wait0() {
    asm volatile("cp.async.wait_group 0;" ::: "memory");
}

// ---------------- K0: reset counters ----------------
__global__ void k_init() {
    if (threadIdx.x < EE) g_cnt[threadIdx.x] = 0;
}

// ---------------- K1: x = concat(hidden, feat @ W_feat + b_feat) + bf16 splits ------
__global__ void k_build_x(const float* __restrict__ hidden,
                          const float* __restrict__ feat,
                          const float* __restrict__ Wf,
                          const float* __restrict__ bf) {
    int tok = blockIdx.x;
    int t = threadIdx.x;
    float v;
    if (t < DD) {
        v = hidden[tok * DD + t];
    } else {
        int j = t - DD;
        float acc = bf[j];
#pragma unroll
        for (int k = 0; k < FF; k++) acc += feat[tok * FF + k] * Wf[k * DFE + j];
        v = acc;
    }
    g_x[tok * DIN + t] = v;
    __nv_bfloat16 h = __float2bfloat16(v);
    g_xh[tok * DIN + t] = h;
    g_xl[tok * DIN + t] = __float2bfloat16(v - __bfloat162float(h));
}

// ---------------- prep: transpose + split expert weights to n-major ----------------
__global__ void k_prep_w1(const float* __restrict__ We1) {
    __shared__ float tile[64][65];
    int e = blockIdx.z, kc = blockIdx.y, hb = blockIdx.x;
    int tid = threadIdx.x;
#pragma unroll
    for (int i = 0; i < 16; i++) {
        int li = i * 256 + tid;
        int ki = li >> 6, hi = li & 63;
        tile[ki][hi] = We1[((size_t)e * DIN + kc * 64 + ki) * DH + hb * 64 + hi];
    }
    __syncthreads();
#pragma unroll
    for (int i = 0; i < 16; i++) {
        int li = i * 256 + tid;
        int kk = li & 63, hr = li >> 6;
        float v = tile[kk][hr];
        __nv_bfloat16 h = __float2bfloat16(v);
        __nv_bfloat16 l = __float2bfloat16(v - __bfloat162float(h));
        size_t dst = (((size_t)(e * 5 + kc) * 512) + hb * 64 + hr) * 64 + kk;
        g_B1h[dst] = h;
        g_B1l[dst] = l;
    }
}

__global__ void k_prep_w2(const float* __restrict__ We2) {
    __shared__ float tile[64][65];
    int e = blockIdx.z, kc = blockIdx.y, ob = blockIdx.x;
    int tid = threadIdx.x;
#pragma unroll
    for (int i = 0; i < 16; i++) {
        int li = i * 256 + tid;
        int ki = li >> 6, oi = li & 63;
        tile[ki][oi] = We2[((size_t)e * DH + kc * 64 + ki) * DD + ob * 64 + oi];
    }
    __syncthreads();
#pragma unroll
    for (int i = 0; i < 16; i++) {
        int li = i * 256 + tid;
        int kk = li & 63, orr = li >> 6;
        float v = tile[kk][orr];
        __nv_bfloat16 h = __float2bfloat16(v);
        __nv_bfloat16 l = __float2bfloat16(v - __bfloat162float(h));
        size_t dst = (((size_t)(e * 8 + kc) * 256) + ob * 64 + orr) * 64 + kk;
        g_B2h[dst] = h;
        g_B2l[dst] = l;
    }
}

// ---------------- K2: router (logit-exact fp32 SIMT) ----------------
#define R_SMEM_FLOATS (320 * 33 + 32 * 256)
__global__ __launch_bounds__(256, 2) void k_router(
    const float* __restrict__ Wr1, const float* __restrict__ br1,
    const float* __restrict__ Wr2, const float* __restrict__ br2,
    float* __restrict__ out) {
    extern __shared__ float sm[];
    float* xT  = sm;
    float* wch = sm + 320 * 33;
    float* hrT = sm;
    float* ws2 = wch;
    float* lg  = wch + 2048;

    int tid  = threadIdx.x;
    int base = blockIdx.x * 32;

    for (int idx = tid; idx < 32 * DIN; idx += 256) {
        int r = idx / DIN;
        int k = idx - r * DIN;
        xT[k * 33 + r] = g_x[(base + r) * DIN + k];
    }

    int tg = tid >> 5;
    int cg = tid & 31;

    float acc[2][4][4];
#pragma unroll
    for (int m = 0; m < 2; m++)
#pragma unroll
        for (int tt = 0; tt < 4; tt++)
#pragma unroll
            for (int j = 0; j < 4; j++) acc[m][tt][j] = 0.f;

    for (int kc = 0; kc < DIN; kc += 32) {
#pragma unroll
        for (int i = 0; i < 32; i++) {
            int idx = tid + i * 256;
            int kk = idx >> 8;
            int c  = idx & 255;
            wch[kk * 256 + c] = Wr1[(kc + kk) * DR + c];
        }
        __syncthreads();
#pragma unroll 2
        for (int k = 0; k < 32; k++) {
            float xv[4];
#pragma unroll
            for (int tt = 0; tt < 4; tt++) xv[tt] = xT[(kc + k) * 33 + 4 * tg + tt];
#pragma unroll
            for (int m = 0; m < 2; m++) {
                float4 wq = *(const float4*)&wch[k * 256 + 128 * m + 4 * cg];
#pragma unroll
                for (int tt = 0; tt < 4; tt++) {
                    acc[m][tt][0] += xv[tt] * wq.x;
                    acc[m][tt][1] += xv[tt] * wq.y;
                    acc[m][tt][2] += xv[tt] * wq.z;
                    acc[m][tt][3] += xv[tt] * wq.w;
                }
            }
        }
        __syncthreads();
    }

#pragma unroll
    for (int m = 0; m < 2; m++)
#pragma unroll
        for (int j = 0; j < 4; j++) {
            int col = 4 * cg + 128 * m + j;
            float b = br1[col];
#pragma unroll
            for (int tt = 0; tt < 4; tt++)
                hrT[col * 33 + 4 * tg + tt] = gelu_tanh(acc[m][tt][j] + b);
        }
    for (int idx = tid; idx < DR * EE; idx += 256) ws2[idx] = Wr2[idx];
    __syncthreads();

    {
        int e = tid >> 5;
        int r = tid & 31;
        float lacc = br2[e];
#pragma unroll 4
        for (int k = 0; k < DR; k++) lacc += hrT[k * 33 + r] * ws2[k * EE + e];
        lg[r * EE + e] = lacc;
        out[(size_t)NT * DD + (size_t)NT * EE + (size_t)(base + r) * EE + e] = lacc;
    }
    __syncthreads();

    if (tid < 32) {
        int r = tid;
        int gtok = base + r;
        float v[EE];
#pragma unroll
        for (int e = 0; e < EE; e++) v[e] = lg[r * EE + e];
        int i0 = 0;
#pragma unroll
        for (int e = 1; e < EE; e++)
            if (v[e] > v[i0]) i0 = e;
        int i1 = (i0 == 0) ? 1 : 0;
#pragma unroll
        for (int e = 0; e < EE; e++) {
            if (e == i0) continue;
            if (v[e] > v[i1]) i1 = e;
        }
        float t  = expf(v[i1] - v[i0]);
        float s  = 1.0f + t;
        float w0 = 1.0f / s;
        float w1 = t / s;
        float* gw = out + (size_t)NT * DD + (size_t)gtok * EE;
#pragma unroll
        for (int e = 0; e < EE; e++)
            gw[e] = (e == i0) ? w0 : ((e == i1) ? w1 : 0.0f);
        int p0 = atomicAdd(&g_cnt[i0], 1);
        g_tok[i0 * NT + p0] = gtok;
        g_w[i0 * NT + p0]   = w0;
        int p1 = atomicAdd(&g_cnt[i1], 1);
        g_tok[i1 * NT + p1] = gtok | (1 << 31);
        g_w[i1 * NT + p1]   = w1;
    }
}

// ---------------- HMMA expert kernels: cp.async double-buffer + ldmatrix ----------------
// Buffer layout (per stage, 73728 B): Ah[128x72bf16] Al Bh Bl, row stride 144 B.
#define BUF_BYTES 73728
#define EXP_SMEM  (2 * BUF_BYTES)

// layer 1: he = gelu(x @ We1 + b1), 20 chunks = nc(4) x kc(5)
__global__ __launch_bounds__(256, 1) void k_expert1(const float* __restrict__ be1) {
    int e = blockIdx.y;
    int cnt = g_cnt[e];
    int base = blockIdx.x * 128;
    if (base >= cnt) return;
    int nrows = min(128, cnt - base);

    extern __shared__ char smraw[];
    uint32_t smb = smem_u32(smraw);

    __shared__ int s_tok[128];
    __shared__ int s_dst[128];

    int tid = threadIdx.x, wid = tid >> 5, lane = tid & 31;
    for (int r = tid; r < 128; r += 256) {
        int rr = (r < nrows) ? r : 0;
        int ent = g_tok[e * NT + base + rr];
        int tok = ent & 0x7FFFFFFF;
        s_tok[r] = tok;
        s_dst[r] = (r < nrows) ? (int)((((unsigned)ent) >> 31) * NT + tok) : -1;
    }
    __syncthreads();

    int wm = wid & 3, wn = wid >> 2, lq = lane >> 2, lr = lane & 3;
    int srow = tid >> 3, su = tid & 7;           // staging: this thread's 4 rows are srow+32*i4
    uint32_t aoff = (uint32_t)((wm * 32 + (lane & 15)) * 144 + ((lane >> 4) << 4));
    uint32_t boff = (uint32_t)((wn * 64 + (lane & 15)) * 144 + ((lane >> 4) << 4));

    float acc[2][8][4];

    // ---- staging lambda ----
    auto stage = [&](int c) {
        int nc = c / 5, kc = c - nc * 5;
        uint32_t b = smb + (uint32_t)(c & 1) * BUF_BYTES;
        const char* Bh = (const char*)(g_B1h + (((size_t)(e * 5 + kc) * 512) + nc * 128) * 64);
        const char* Bl = (const char*)(g_B1l + (((size_t)(e * 5 + kc) * 512) + nc * 128) * 64);
#pragma unroll
        for (int i4 = 0; i4 < 4; i4++) {
            int r = srow + i4 * 32;
            uint32_t d = b + (uint32_t)(r * 144 + su * 16);
            size_t sb = (size_t)s_tok[r] * DIN + kc * 64;
            cp16(d,         (const char*)(g_xh + sb) + su * 16);
            cp16(d + 18432, (const char*)(g_xl + sb) + su * 16);
            cp16(d + 36864, Bh + r * 128 + su * 16);
            cp16(d + 55296, Bl + r * 128 + su * 16);
        }
        cp_commit();
    };

    stage(0);
    for (int c = 0; c < 20; c++) {
        int nc = c / 5, kc = c - nc * 5;
        if (c + 1 < 20) { stage(c + 1); cp_wait1(); } else { cp_wait0(); }
        __syncthreads();
        uint32_t b = smb + (uint32_t)(c & 1) * BUF_BYTES;

        if (kc == 0) {
#pragma unroll
            for (int mt = 0; mt < 2; mt++)
#pragma unroll
                for (int nt = 0; nt < 8; nt++)
#pragma unroll
                    for (int j = 0; j < 4; j++) acc[mt][nt][j] = 0.f;
        }
#pragma unroll
        for (int s = 0; s < 4; s++) {
            uint32_t ah[2][4], al[2][4];
#pragma unroll
            for (int mt = 0; mt < 2; mt++) {
                uint32_t a = b + aoff + (uint32_t)(mt * 2304 + s * 32);
                ldsm_x4(ah[mt], a);
                ldsm_x4(al[mt], a + 18432);
            }
#pragma unroll
            for (int g = 0; g < 4; g++) {
                uint32_t bh[4], bl[4];
                uint32_t a = b + 36864 + boff + (uint32_t)(g * 2304 + s * 32);
                ldsm_x4(bh, a);
                ldsm_x4(bl, a + 18432);
                uint32_t bhe[2] = {bh[0], bh[2]}, bho[2] = {bh[1], bh[3]};
                uint32_t ble[2] = {bl[0], bl[2]}, blo[2] = {bl[1], bl[3]};
#pragma unroll
                for (int mt = 0; mt < 2; mt++) {
                    mma_bf16(acc[mt][2 * g],     ah[mt], bhe);
                    mma_bf16(acc[mt][2 * g],     ah[mt], ble);
                    mma_bf16(acc[mt][2 * g],     al[mt], bhe);
                    mma_bf16(acc[mt][2 * g + 1], ah[mt], bho);
                    mma_bf16(acc[mt][2 * g + 1], ah[mt], blo);
                    mma_bf16(acc[mt][2 * g + 1], al[mt], bho);
                }
            }
        }

        if (kc == 4) {
            const float* b1 = be1 + e * DH + nc * 128;
#pragma unroll
            for (int mt = 0; mt < 2; mt++)
#pragma unroll
                for (int nt = 0; nt < 8; nt++) {
                    int col = wn * 64 + nt * 8 + lr * 2;
                    float bb0 = b1[col], bb1 = b1[col + 1];
#pragma unroll
                    for (int h = 0; h < 2; h++) {
                        int row = wm * 32 + mt * 16 + lq + h * 8;
                        int dst = s_dst[row];
                        if (dst >= 0) {
                            float v0 = gelu_fast(acc[mt][nt][2 * h]     + bb0);
                            float v1 = gelu_fast(acc[mt][nt][2 * h + 1] + bb1);
                            __nv_bfloat16 h0 = __float2bfloat16(v0), h1 = __float2bfloat16(v1);
                            __nv_bfloat16 l0 = __float2bfloat16(v0 - __bfloat162float(h0));
                            __nv_bfloat16 l1 = __float2bfloat16(v1 - __bfloat162float(h1));
                            uint32_t ph = (uint32_t)__bfloat16_as_ushort(h0) | ((uint32_t)__bfloat16_as_ushort(h1) << 16);
                            uint32_t pl = (uint32_t)__bfloat16_as_ushort(l0) | ((uint32_t)__bfloat16_as_ushort(l1) << 16);
                            size_t widx = ((size_t)dst * DH + nc * 128 + col) >> 1;
                            ((uint32_t*)g_heh)[widx] = ph;
                            ((uint32_t*)g_hel)[widx] = pl;
                        }
                    }
                }
        }
        __syncthreads();
    }
}

// layer 2: eo = he @ We2 + b2, gate-scaled; 16 chunks = nc(2) x kc(8)
__global__ __launch_bounds__(256, 1) void k_expert2(const float* __restrict__ be2) {
    int e = blockIdx.y;
    int cnt = g_cnt[e];
    int base = blockIdx.x * 128;
    if (base >= cnt) return;
    int nrows = min(128, cnt - base);

    extern __shared__ char smraw[];
    uint32_t smb = smem_u32(smraw);

    __shared__ int   s_row[128];
    __shared__ int   s_dst[128];
    __shared__ float s_w[128];

    int tid = threadIdx.x, wid = tid >> 5, lane = tid & 31;
    for (int r = tid; r < 128; r += 256) {
        int rr = (r < nrows) ? r : 0;
        int ent = g_tok[e * NT + base + rr];
        int tok = ent & 0x7FFFFFFF;
        int herow = (int)((((unsigned)ent) >> 31) * NT + tok);
        s_row[r] = herow;
        s_dst[r] = (r < nrows) ? herow : -1;
        s_w[r]   = g_w[e * NT + base + rr];
    }
    __syncthreads();

    int wm = wid & 3, wn = wid >> 2, lq = lane >> 2, lr = lane & 3;
    int srow = tid >> 3, su = tid & 7;
    uint32_t aoff = (uint32_t)((wm * 32 + (lane & 15)) * 144 + ((lane >> 4) << 4));
    uint32_t boff = (uint32_t)((wn * 64 + (lane & 15)) * 144 + ((lane >> 4) << 4));

    float acc[2][8][4];

    auto stage = [&](int c) {
        int nc = c >> 3, kc = c & 7;
        uint32_t b = smb + (uint32_t)(c & 1) * BUF_BYTES;
        const char* Bh = (const char*)(g_B2h + (((size_t)(e * 8 + kc) * 256) + nc * 128) * 64);
        const char* Bl = (const char*)(g_B2l + (((size_t)(e * 8 + kc) * 256) + nc * 128) * 64);
#pragma unroll
        for (int i4 = 0; i4 < 4; i4++) {
            int r = srow + i4 * 32;
            uint32_t d = b + (uint32_t)(r * 144 + su * 16);
            size_t sb = (size_t)s_row[r] * DH + kc * 64;
            cp16(d,         (const char*)(g_heh + sb) + su * 16);
            cp16(d + 18432, (const char*)(g_hel + sb) + su * 16);
            cp16(d + 36864, Bh + r * 128 + su * 16);
            cp16(d + 55296, Bl + r * 128 + su * 16);
        }
        cp_commit();
    };

    stage(0);
    for (int c = 0; c < 16; c++) {
        int nc = c >> 3, kc = c & 7;
        if (c + 1 < 16) { stage(c + 1); cp_wait1(); } else { cp_wait0(); }
        __syncthreads();
        uint32_t b = smb + (uint32_t)(c & 1) * BUF_BYTES;

        if (kc == 0) {
#pragma unroll
            for (int mt = 0; mt < 2; mt++)
#pragma unroll
                for (int nt = 0; nt < 8; nt++)
#pragma unroll
                    for (int j = 0; j < 4; j++) acc[mt][nt][j] = 0.f;
        }
#pragma unroll
        for (int s = 0; s < 4; s++) {
            uint32_t ah[2][4], al[2][4];
#pragma unroll
            for (int mt = 0; mt < 2; mt++) {
                uint32_t a = b + aoff + (uint32_t)(mt * 2304 + s * 32);
                ldsm_x4(ah[mt], a);
                ldsm_x4(al[mt], a + 18432);
            }
#pragma unroll
            for (int g = 0; g < 4; g++) {
                uint32_t bh[4], bl[4];
                uint32_t a = b + 36864 + boff + (uint32_t)(g * 2304 + s * 32);
                ldsm_x4(bh, a);
                ldsm_x4(bl, a + 18432);
                uint32_t bhe[2] = {bh[0], bh[2]}, bho[2] = {bh[1], bh[3]};
                uint32_t ble[2] = {bl[0], bl[2]}, blo[2] = {bl[1], bl[3]};
#pragma unroll
                for (int mt = 0; mt < 2; mt++) {
                    mma_bf16(acc[mt][2 * g],     ah[mt], bhe);
                    mma_bf16(acc[mt][2 * g],     ah[mt], ble);
                    mma_bf16(acc[mt][2 * g],     al[mt], bhe);
                    mma_bf16(acc[mt][2 * g + 1], ah[mt], bho);
                    mma_bf16(acc[mt][2 * g + 1], ah[mt], blo);
                    mma_bf16(acc[mt][2 * g + 1], al[mt], bho);
                }
            }
        }

        if (kc == 7) {
            const float* b2 = be2 + e * DD + nc * 128;
#pragma unroll
            for (int mt = 0; mt < 2; mt++)
#pragma unroll
                for (int nt = 0; nt < 8; nt++) {
                    int col = wn * 64 + nt * 8 + lr * 2;
                    float bb0 = b2[col], bb1 = b2[col + 1];
#pragma unroll
                    for (int h = 0; h < 2; h++) {
                        int row = wm * 32 + mt * 16 + lq + h * 8;
                        int dst = s_dst[row];
                        if (dst >= 0) {
                            float wgt = s_w[row];
                            float2 o;
                            o.x = wgt * (acc[mt][nt][2 * h]     + bb0);
                            o.y = wgt * (acc[mt][nt][2 * h + 1] + bb1);
                            *(float2*)&g_part[(size_t)dst * DD + nc * 128 + col] = o;
                        }
                    }
                }
        }
        __syncthreads();
    }
}

// ---------------- K4: combine slot partials ----------------
__global__ void k_combine(float* __restrict__ out) {
    int i = blockIdx.x * blockDim.x + threadIdx.x;
    const float4* p0 = (const float4*)g_part;
    const float4* p1 = (const float4*)(g_part + (size_t)NT * DD);
    float4 a = p0[i], b = p1[i];
    float4 r;
    r.x = a.x + b.x; r.y = a.y + b.y; r.z = a.z + b.z; r.w = a.w + b.w;
    ((float4*)out)[i] = r;
}

// ---------------- launch ----------------
extern "C" void kernel_launch(void* const* d_in, const int* in_sizes, int n_in,
                              void* d_out, int out_size) {
    const float* hidden = (const float*)d_in[0];
    const float* feat   = (const float*)d_in[1];
    const float* Wf     = (const float*)d_in[2];
    const float* bf     = (const float*)d_in[3];
    const float* Wr1    = (const float*)d_in[4];
    const float* br1    = (const float*)d_in[5];
    const float* Wr2    = (const float*)d_in[6];
    const float* br2    = (const float*)d_in[7];
    const float* We1    = (const float*)d_in[8];
    const float* be1    = (const float*)d_in[9];
    const float* We2    = (const float*)d_in[10];
    const float* be2    = (const float*)d_in[11];
    float* out = (float*)d_out;

    const int r_smem = R_SMEM_FLOATS * 4;
    cudaFuncSetAttribute(k_router,  cudaFuncAttributeMaxDynamicSharedMemorySize, r_smem);
    cudaFuncSetAttribute(k_expert1, cudaFuncAttributeMaxDynamicSharedMemorySize, EXP_SMEM);
    cudaFuncSetAttribute(k_expert2, cudaFuncAttributeMaxDynamicSharedMemorySize, EXP_SMEM);

    k_init<<<1, 32>>>();
    k_build_x<<<NT, DIN>>>(hidden, feat, Wf, bf);
    k_prep_w1<<<dim3(8, 5, EE), 256>>>(We1);
    k_prep_w2<<<dim3(4, 8, EE), 256>>>(We2);
    k_router<<<NT / 32, 256, r_smem>>>(Wr1, br1, Wr2, br2, out);
    k_expert1<<<dim3(64, EE), 256, EXP_SMEM>>>(be1);
    k_expert2<<<dim3(64, EE), 256, EXP_SMEM>>>(be2);
    k_combine<<<(NT * DD / 4) / 256, 256>>>(out);
}